// round 1
// baseline (speedup 1.0000x reference)
#include <cuda_runtime.h>
#include <cstdint>
#include <cstddef>

#define B_  4
#define S_  2048
#define D_  512
#define H_  8
#define DEPTH 64
#define BH  (B_*H_)

// ---------------- scratch (no allocations allowed) ----------------
__device__ float g_Q[(size_t)BH*S_*DEPTH];    // Q'  head-split (bh, s, d)
__device__ float g_K[(size_t)BH*S_*DEPTH];    // K'' = k@Wk + pos@Wd (head-split)
__device__ float g_V[(size_t)BH*S_*DEPTH];    // V'  head-split
__device__ float g_ctx[(size_t)B_*S_*D_];     // ctx in (B,S,D) layout
__device__ float g_rsinv[(size_t)BH*S_];      // 1/rowsum

// ---------------- tf32 mma helpers ----------------
__device__ __forceinline__ uint32_t f2tf(float x){
    uint32_t u; asm("cvt.rna.tf32.f32 %0, %1;" : "=r"(u) : "f"(x)); return u;
}
__device__ __forceinline__ void mma8(float c[4], uint32_t a0,uint32_t a1,uint32_t a2,uint32_t a3,
                                     uint32_t b0,uint32_t b1){
    asm volatile("mma.sync.aligned.m16n8k8.row.col.f32.tf32.tf32.f32 "
        "{%0,%1,%2,%3}, {%4,%5,%6,%7}, {%8,%9}, {%0,%1,%2,%3};"
        : "+f"(c[0]),"+f"(c[1]),"+f"(c[2]),"+f"(c[3])
        : "r"(a0),"r"(a1),"r"(a2),"r"(a3),"r"(b0),"r"(b1));
}

// ---------------- generic projection GEMM ----------------
// C = A(8192x512) @ B(512x512 row-major) + bias  [+ C if BETA]
// SPLIT: write C head-split (b,h,s,d); else plain row-major 8192x512.
template<int SPLIT, int BETA>
__global__ __launch_bounds__(256)
void gemm_proj(const float* __restrict__ A, const float* __restrict__ Bm,
               const float* __restrict__ bias, float* __restrict__ C)
{
    const int N = 512, K = 512;
    __shared__ float As[128][36];   // pad 4: stride 36 -> 4g+t conflict-free
    __shared__ float Bs[32][72];    // pad 8: stride 72 -> 8t+g conflict-free

    int tid = threadIdx.x;
    int lane = tid & 31, wid = tid >> 5;
    int g = lane >> 2, tg = lane & 3;
    int wm = wid & 3, wn = wid >> 2;          // 4x2 warps -> CTA tile 128x64
    int m0 = blockIdx.y * 128, n0 = blockIdx.x * 64;

    float acc[2][4][4];
    #pragma unroll
    for (int i=0;i<2;i++)
        #pragma unroll
        for (int j=0;j<4;j++)
            #pragma unroll
            for (int r=0;r<4;r++) acc[i][j][r]=0.f;

    for (int k0 = 0; k0 < K; k0 += 32){
        #pragma unroll
        for (int i=0;i<4;i++){                 // A: 128x32
            int e = tid + i*256;
            int r = e>>3, c = (e&7)*4;
            *(float4*)&As[r][c] = *(const float4*)(A + (size_t)(m0+r)*K + k0 + c);
        }
        #pragma unroll
        for (int i=0;i<2;i++){                 // B: 32x64
            int e = tid + i*256;
            int r = e>>4, c = (e&15)*4;
            *(float4*)&Bs[r][c] = *(const float4*)(Bm + (size_t)(k0+r)*N + n0 + c);
        }
        __syncthreads();
        #pragma unroll
        for (int kk=0; kk<32; kk+=8){
            uint32_t af[2][4];
            #pragma unroll
            for (int mi=0;mi<2;mi++){
                int rb = wm*32 + mi*16;
                af[mi][0]=f2tf(As[rb+g  ][kk+tg  ]);
                af[mi][1]=f2tf(As[rb+g+8][kk+tg  ]);
                af[mi][2]=f2tf(As[rb+g  ][kk+tg+4]);
                af[mi][3]=f2tf(As[rb+g+8][kk+tg+4]);
            }
            #pragma unroll
            for (int ni=0;ni<4;ni++){
                int cb = wn*32 + ni*8 + g;
                uint32_t b0=f2tf(Bs[kk+tg  ][cb]);
                uint32_t b1=f2tf(Bs[kk+tg+4][cb]);
                mma8(acc[0][ni], af[0][0],af[0][1],af[0][2],af[0][3], b0,b1);
                mma8(acc[1][ni], af[1][0],af[1][1],af[1][2],af[1][3], b0,b1);
            }
        }
        __syncthreads();
    }

    #pragma unroll
    for (int mi=0;mi<2;mi++)
        #pragma unroll
        for (int ni=0;ni<4;ni++)
            #pragma unroll
            for (int half=0; half<2; half++){
                int row = m0 + wm*32 + mi*16 + g + half*8;
                int col = n0 + wn*32 + ni*8 + tg*2;
                float v0 = acc[mi][ni][half*2+0] + bias[col];
                float v1 = acc[mi][ni][half*2+1] + bias[col+1];
                size_t idx;
                if (SPLIT){
                    int b = row >> 11, s = row & 2047;
                    int h = col >> 6,  d = col & 63;
                    idx = (((size_t)(b*H_ + h))*S_ + s)*DEPTH + d;
                } else {
                    idx = (size_t)row*N + col;
                }
                if (BETA){ v0 += C[idx]; v1 += C[idx+1]; }
                C[idx]   = v0;
                C[idx+1] = v1;
            }
}

// ---------------- pass 1: rowsum of exp(logits) ----------------
__global__ __launch_bounds__(256)
void attn_rowsum(const float* __restrict__ Q, const float* __restrict__ Kp,
                 float* __restrict__ rsinv)
{
    extern __shared__ float sm[];
    float (*Qs)[68] = (float(*)[68])sm;                 // 128x68
    float (*Ks)[68] = (float(*)[68])(sm + 128*68);      // 64x68
    float *rs = sm + 128*68 + 64*68;                    // 128

    int tid = threadIdx.x;
    int lane = tid & 31, wid = tid >> 5;
    int g = lane >> 2, tg = lane & 3;
    int wm = wid & 3, wn = wid >> 2;
    int bh = blockIdx.y;
    int s0 = blockIdx.x * 128;

    const float* Qb = Q  + ((size_t)bh*S_ + s0)*DEPTH;
    const float* Kb = Kp +  (size_t)bh*S_*DEPTH;

    #pragma unroll
    for (int i=0;i<8;i++){
        int e = tid + i*256;
        int r = e>>4, c = (e&15)*4;
        *(float4*)&Qs[r][c] = *(const float4*)(Qb + (size_t)r*DEPTH + c);
    }
    if (tid < 128) rs[tid] = 0.f;
    __syncthreads();

    float rowacc[4] = {0.f,0.f,0.f,0.f};

    for (int t0 = 0; t0 < S_; t0 += 64){
        #pragma unroll
        for (int i=0;i<4;i++){
            int e = tid + i*256;
            int r = e>>4, c = (e&15)*4;
            *(float4*)&Ks[r][c] = *(const float4*)(Kb + (size_t)(t0+r)*DEPTH + c);
        }
        __syncthreads();

        float acc[2][4][4];
        #pragma unroll
        for (int i=0;i<2;i++)
            #pragma unroll
            for (int j=0;j<4;j++)
                #pragma unroll
                for (int r=0;r<4;r++) acc[i][j][r]=0.f;

        #pragma unroll
        for (int kk=0; kk<64; kk+=8){
            uint32_t af[2][4];
            #pragma unroll
            for (int mi=0;mi<2;mi++){
                int rb = wm*32 + mi*16;
                af[mi][0]=f2tf(Qs[rb+g  ][kk+tg  ]);
                af[mi][1]=f2tf(Qs[rb+g+8][kk+tg  ]);
                af[mi][2]=f2tf(Qs[rb+g  ][kk+tg+4]);
                af[mi][3]=f2tf(Qs[rb+g+8][kk+tg+4]);
            }
            #pragma unroll
            for (int ni=0;ni<4;ni++){
                int cb = wn*32 + ni*8 + g;        // t index
                uint32_t b0=f2tf(Ks[cb][kk+tg  ]);
                uint32_t b1=f2tf(Ks[cb][kk+tg+4]);
                mma8(acc[0][ni], af[0][0],af[0][1],af[0][2],af[0][3], b0,b1);
                mma8(acc[1][ni], af[1][0],af[1][1],af[1][2],af[1][3], b0,b1);
            }
        }
        #pragma unroll
        for (int mi=0;mi<2;mi++)
            #pragma unroll
            for (int ni=0;ni<4;ni++)
                #pragma unroll
                for (int r2=0;r2<4;r2++){
                    float e_ = __expf(acc[mi][ni][r2]*0.125f);
                    rowacc[mi*2 + (r2>>1)] += e_;
                }
        __syncthreads();   // before Ks is overwritten
    }

    #pragma unroll
    for (int i=0;i<4;i++){
        float v = rowacc[i];
        v += __shfl_xor_sync(0xffffffffu, v, 1);
        v += __shfl_xor_sync(0xffffffffu, v, 2);
        if (tg == 0){
            int row = wm*32 + (i>>1)*16 + g + (i&1)*8;
            atomicAdd(&rs[row], v);
        }
    }
    __syncthreads();
    if (tid < 128) rsinv[(size_t)bh*S_ + s0 + tid] = 1.0f / rs[tid];
}

// ---------------- pass 2: attn write + ctx = attn @ V ----------------
__global__ __launch_bounds__(256)
void attn_pv(const float* __restrict__ Q, const float* __restrict__ Kp,
             const float* __restrict__ V, const float* __restrict__ rsinv,
             float* __restrict__ attn, float* __restrict__ ctx)
{
    extern __shared__ float sm[];
    float (*Qs)[68] = (float(*)[68])sm;                          // 128x68
    float (*Ks)[68] = (float(*)[68])(sm + 128*68);               // 64x68
    float (*Ps)[68] = (float(*)[68])(sm + 128*68 + 64*68);       // 128x68
    float (*Vs)[72] = (float(*)[72])(sm + 128*68 + 64*68 + 128*68); // 64x72
    float *rsv = sm + 128*68 + 64*68 + 128*68 + 64*72;           // 128

    int tid = threadIdx.x;
    int lane = tid & 31, wid = tid >> 5;
    int g = lane >> 2, tg = lane & 3;
    int wm = wid & 3, wn = wid >> 2;
    int bh = blockIdx.y;
    int s0 = blockIdx.x * 128;

    const float* Qb = Q  + ((size_t)bh*S_ + s0)*DEPTH;
    const float* Kb = Kp +  (size_t)bh*S_*DEPTH;
    const float* Vb = V  +  (size_t)bh*S_*DEPTH;

    #pragma unroll
    for (int i=0;i<8;i++){
        int e = tid + i*256;
        int r = e>>4, c = (e&15)*4;
        *(float4*)&Qs[r][c] = *(const float4*)(Qb + (size_t)r*DEPTH + c);
    }
    if (tid < 128) rsv[tid] = rsinv[(size_t)bh*S_ + s0 + tid];
    __syncthreads();

    float octx[2][4][4];
    #pragma unroll
    for (int i=0;i<2;i++)
        #pragma unroll
        for (int j=0;j<4;j++)
            #pragma unroll
            for (int r=0;r<4;r++) octx[i][j][r]=0.f;

    for (int t0 = 0; t0 < S_; t0 += 64){
        #pragma unroll
        for (int i=0;i<4;i++){
            int e = tid + i*256;
            int r = e>>4, c = (e&15)*4;
            *(float4*)&Ks[r][c] = *(const float4*)(Kb + (size_t)(t0+r)*DEPTH + c);
            *(float4*)&Vs[r][c] = *(const float4*)(Vb + (size_t)(t0+r)*DEPTH + c);
        }
        __syncthreads();

        float acc[2][4][4];
        #pragma unroll
        for (int i=0;i<2;i++)
            #pragma unroll
            for (int j=0;j<4;j++)
                #pragma unroll
                for (int r=0;r<4;r++) acc[i][j][r]=0.f;

        // logits = Q @ K''^T
        #pragma unroll
        for (int kk=0; kk<64; kk+=8){
            uint32_t af[2][4];
            #pragma unroll
            for (int mi=0;mi<2;mi++){
                int rb = wm*32 + mi*16;
                af[mi][0]=f2tf(Qs[rb+g  ][kk+tg  ]);
                af[mi][1]=f2tf(Qs[rb+g+8][kk+tg  ]);
                af[mi][2]=f2tf(Qs[rb+g  ][kk+tg+4]);
                af[mi][3]=f2tf(Qs[rb+g+8][kk+tg+4]);
            }
            #pragma unroll
            for (int ni=0;ni<4;ni++){
                int cb = wn*32 + ni*8 + g;
                uint32_t b0=f2tf(Ks[cb][kk+tg  ]);
                uint32_t b1=f2tf(Ks[cb][kk+tg+4]);
                mma8(acc[0][ni], af[0][0],af[0][1],af[0][2],af[0][3], b0,b1);
                mma8(acc[1][ni], af[1][0],af[1][1],af[1][2],af[1][3], b0,b1);
            }
        }

        // p = exp(l/8) / rowsum
        #pragma unroll
        for (int mi=0;mi<2;mi++){
            int r0 = wm*32 + mi*16 + g;
            float inv0 = rsv[r0], inv1 = rsv[r0+8];
            #pragma unroll
            for (int ni=0;ni<4;ni++){
                acc[mi][ni][0] = __expf(acc[mi][ni][0]*0.125f)*inv0;
                acc[mi][ni][1] = __expf(acc[mi][ni][1]*0.125f)*inv0;
                acc[mi][ni][2] = __expf(acc[mi][ni][2]*0.125f)*inv1;
                acc[mi][ni][3] = __expf(acc[mi][ni][3]*0.125f)*inv1;
            }
        }

        // write normalized attn tile + stage P in smem
        #pragma unroll
        for (int mi=0;mi<2;mi++)
            #pragma unroll
            for (int ni=0;ni<4;ni++)
                #pragma unroll
                for (int half=0; half<2; half++){
                    int rloc = wm*32 + mi*16 + g + half*8;
                    int cloc = wn*32 + ni*8 + tg*2;
                    float2 v2 = make_float2(acc[mi][ni][half*2], acc[mi][ni][half*2+1]);
                    *(float2*)&Ps[rloc][cloc] = v2;
                    size_t aidx = ((size_t)bh*S_ + s0 + rloc)*S_ + t0 + cloc;
                    *(float2*)(attn + aidx) = v2;
                }
        __syncthreads();   // P complete before PV mma

        // ctx += P @ V
        #pragma unroll
        for (int kk=0; kk<64; kk+=8){
            uint32_t af[2][4];
            #pragma unroll
            for (int mi=0;mi<2;mi++){
                int rb = wm*32 + mi*16;
                af[mi][0]=f2tf(Ps[rb+g  ][kk+tg  ]);
                af[mi][1]=f2tf(Ps[rb+g+8][kk+tg  ]);
                af[mi][2]=f2tf(Ps[rb+g  ][kk+tg+4]);
                af[mi][3]=f2tf(Ps[rb+g+8][kk+tg+4]);
            }
            #pragma unroll
            for (int ni=0;ni<4;ni++){
                int cb = wn*32 + ni*8 + g;       // d index
                uint32_t b0=f2tf(Vs[kk+tg  ][cb]);
                uint32_t b1=f2tf(Vs[kk+tg+4][cb]);
                mma8(octx[0][ni], af[0][0],af[0][1],af[0][2],af[0][3], b0,b1);
                mma8(octx[1][ni], af[1][0],af[1][1],af[1][2],af[1][3], b0,b1);
            }
        }
        __syncthreads();   // before Ks/Vs overwritten next iter
    }

    // write ctx in (B,S,D) layout
    int b = bh >> 3, h = bh & 7;
    #pragma unroll
    for (int mi=0;mi<2;mi++)
        #pragma unroll
        for (int ni=0;ni<4;ni++)
            #pragma unroll
            for (int half=0; half<2; half++){
                int row = s0 + wm*32 + mi*16 + g + half*8;
                int col = h*64 + wn*32 + ni*8 + tg*2;
                float2 v2 = make_float2(octx[mi][ni][half*2], octx[mi][ni][half*2+1]);
                *(float2*)(ctx + ((size_t)b*S_ + row)*D_ + col) = v2;
            }
}

// ---------------- launch ----------------
extern "C" void kernel_launch(void* const* d_in, const int* in_sizes, int n_in,
                              void* d_out, int out_size)
{
    const float* q   = (const float*)d_in[0];
    const float* k   = (const float*)d_in[1];
    const float* v   = (const float*)d_in[2];
    const float* pe  = (const float*)d_in[3];
    // d_in[4] = mask (unused by reference)
    const float* Wq  = (const float*)d_in[5];
    const float* bq  = (const float*)d_in[6];
    const float* Wk  = (const float*)d_in[7];
    const float* bk  = (const float*)d_in[8];
    const float* Wv  = (const float*)d_in[9];
    const float* bv  = (const float*)d_in[10];
    const float* Wd  = (const float*)d_in[11];
    const float* bd  = (const float*)d_in[12];

    float* out  = (float*)d_out;                       // (B,S,D)
    float* attn = out + (size_t)B_*S_*D_;              // (B,H,S,S)

    float *Qp, *Kp, *Vp, *Ctx, *Rs;
    cudaGetSymbolAddress((void**)&Qp,  g_Q);
    cudaGetSymbolAddress((void**)&Kp,  g_K);
    cudaGetSymbolAddress((void**)&Vp,  g_V);
    cudaGetSymbolAddress((void**)&Ctx, g_ctx);
    cudaGetSymbolAddress((void**)&Rs,  g_rsinv);

    dim3 gg(8, 64), bb(256);
    gemm_proj<1,0><<<gg, bb>>>(q,  Wq, bq, Qp);
    gemm_proj<1,0><<<gg, bb>>>(k,  Wk, bk, Kp);
    gemm_proj<1,1><<<gg, bb>>>(pe, Wd, bd, Kp);   // K'' = K' + PE
    gemm_proj<1,0><<<gg, bb>>>(v,  Wv, bv, Vp);

    size_t sm2 = (size_t)(128*68 + 64*68 + 128) * sizeof(float);
    cudaFuncSetAttribute(attn_rowsum, cudaFuncAttributeMaxDynamicSharedMemorySize, (int)sm2);
    attn_rowsum<<<dim3(16, BH), 256, sm2>>>(Qp, Kp, Rs);

    size_t sm3 = (size_t)(128*68 + 64*68 + 128*68 + 64*72 + 128) * sizeof(float);
    cudaFuncSetAttribute(attn_pv, cudaFuncAttributeMaxDynamicSharedMemorySize, (int)sm3);
    attn_pv<<<dim3(16, BH), 256, sm3>>>(Qp, Kp, Vp, Rs, attn, Ctx);

    gemm_proj<0,0><<<gg, bb>>>(Ctx, Wd, bd, out);
}

// round 2
// speedup vs baseline: 1.2905x; 1.2905x over previous
#include <cuda_runtime.h>
#include <cstdint>
#include <cstddef>

#define B_  4
#define S_  2048
#define D_  512
#define H_  8
#define DEPTH 64
#define BH  (B_*H_)

// ---------------- scratch (no allocations allowed) ----------------
__device__ float g_Q[(size_t)BH*S_*DEPTH];    // Q'  head-split (bh, s, d)
__device__ float g_K[(size_t)BH*S_*DEPTH];    // K'' = k@Wk + pos@Wd (head-split)
__device__ float g_V[(size_t)BH*S_*DEPTH];    // V'  head-split
__device__ float g_ctx[(size_t)B_*S_*D_];     // ctx in (B,S,D) layout
__device__ float g_rsinv[(size_t)BH*S_];      // 1/rowsum

// ---------------- tf32 helpers ----------------
__device__ __forceinline__ uint32_t f2tf(float x){
    uint32_t u; asm("cvt.rna.tf32.f32 %0, %1;" : "=r"(u) : "f"(x)); return u;
}
__device__ __forceinline__ uint4 tf4(float4 v){
    return make_uint4(f2tf(v.x), f2tf(v.y), f2tf(v.z), f2tf(v.w));
}
__device__ __forceinline__ void mma8(float c[4], uint32_t a0,uint32_t a1,uint32_t a2,uint32_t a3,
                                     uint32_t b0,uint32_t b1){
    asm volatile("mma.sync.aligned.m16n8k8.row.col.f32.tf32.tf32.f32 "
        "{%0,%1,%2,%3}, {%4,%5,%6,%7}, {%8,%9}, {%0,%1,%2,%3};"
        : "+f"(c[0]),"+f"(c[1]),"+f"(c[2]),"+f"(c[3])
        : "r"(a0),"r"(a1),"r"(a2),"r"(a3),"r"(b0),"r"(b1));
}

// ---------------- shared GEMM core ----------------
// C[128x64 tile] = A1@B1 (+ A2@B2 if A2) + bias1 (+ bias2)
// A: 8192x512 row-major, B: 512x512 row-major. SMEM tiles hold PRE-CONVERTED tf32.
// split: write head-split (b,h,s,d); else row-major 8192x512.
__device__ __forceinline__ void gemm_core(
    const float* __restrict__ A1, const float* __restrict__ B1, const float* __restrict__ bias1,
    const float* __restrict__ A2, const float* __restrict__ B2, const float* __restrict__ bias2,
    float* __restrict__ C, int split, int m0, int n0,
    uint32_t (*As)[36], uint32_t (*Bs)[72])
{
    int tid = threadIdx.x;
    int lane = tid & 31, wid = tid >> 5;
    int g = lane >> 2, tg = lane & 3;
    int wm = wid & 3, wn = wid >> 2;          // 4x2 warps -> CTA tile 128x64

    float acc[2][4][4];
    #pragma unroll
    for (int i=0;i<2;i++)
        #pragma unroll
        for (int j=0;j<4;j++)
            #pragma unroll
            for (int r=0;r<4;r++) acc[i][j][r]=0.f;

    const int ntile = A2 ? 32 : 16;           // 32-deep k tiles

    float4 ra[4]; float4 rb[2];
    auto ldg_tile = [&](int t){
        const float* A  = (t >= 16) ? A2 : A1;
        const float* Bm = (t >= 16) ? B2 : B1;
        int k0 = (t & 15) * 32;
        #pragma unroll
        for (int i=0;i<4;i++){                 // A: 128x32
            int e = tid + i*256;
            int r = e>>3, c = (e&7)*4;
            ra[i] = *(const float4*)(A + (size_t)(m0+r)*512 + k0 + c);
        }
        #pragma unroll
        for (int i=0;i<2;i++){                 // B: 32x64
            int e = tid + i*256;
            int r = e>>4, c = (e&15)*4;
            rb[i] = *(const float4*)(Bm + (size_t)(k0+r)*512 + n0 + c);
        }
    };

    ldg_tile(0);
    for (int t = 0; t < ntile; t++){
        #pragma unroll
        for (int i=0;i<4;i++){
            int e = tid + i*256;
            int r = e>>3, c = (e&7)*4;
            *(uint4*)&As[r][c] = tf4(ra[i]);
        }
        #pragma unroll
        for (int i=0;i<2;i++){
            int e = tid + i*256;
            int r = e>>4, c = (e&15)*4;
            *(uint4*)&Bs[r][c] = tf4(rb[i]);
        }
        __syncthreads();
        if (t+1 < ntile) ldg_tile(t+1);        // overlap LDG with mma
        #pragma unroll
        for (int kk=0; kk<32; kk+=8){
            uint32_t af[2][4];
            #pragma unroll
            for (int mi=0;mi<2;mi++){
                int rb_ = wm*32 + mi*16;
                af[mi][0]=As[rb_+g  ][kk+tg  ];
                af[mi][1]=As[rb_+g+8][kk+tg  ];
                af[mi][2]=As[rb_+g  ][kk+tg+4];
                af[mi][3]=As[rb_+g+8][kk+tg+4];
            }
            #pragma unroll
            for (int ni=0;ni<4;ni++){
                int cb = wn*32 + ni*8 + g;
                uint32_t b0=Bs[kk+tg  ][cb];
                uint32_t b1=Bs[kk+tg+4][cb];
                mma8(acc[0][ni], af[0][0],af[0][1],af[0][2],af[0][3], b0,b1);
                mma8(acc[1][ni], af[1][0],af[1][1],af[1][2],af[1][3], b0,b1);
            }
        }
        __syncthreads();
    }

    #pragma unroll
    for (int mi=0;mi<2;mi++)
        #pragma unroll
        for (int ni=0;ni<4;ni++)
            #pragma unroll
            for (int half=0; half<2; half++){
                int row = m0 + wm*32 + mi*16 + g + half*8;
                int col = n0 + wn*32 + ni*8 + tg*2;
                float b0v = bias1[col]   + (bias2 ? bias2[col]   : 0.f);
                float b1v = bias1[col+1] + (bias2 ? bias2[col+1] : 0.f);
                float v0 = acc[mi][ni][half*2+0] + b0v;
                float v1 = acc[mi][ni][half*2+1] + b1v;
                size_t idx;
                if (split){
                    int b = row >> 11, s = row & 2047;
                    int h = col >> 6,  d = col & 63;
                    idx = (((size_t)(b*H_ + h))*S_ + s)*DEPTH + d;
                } else {
                    idx = (size_t)row*512 + col;
                }
                *(float2*)(C + idx) = make_float2(v0, v1);
            }
}

// z=0: Q'=q@Wq+bq   z=1: K''=k@Wk+pe@Wd+bk+bd   z=2: V'=v@Wv+bv
__global__ __launch_bounds__(256)
void proj3(const float* q, const float* k, const float* pe, const float* v,
           const float* Wq, const float* Wk, const float* Wv, const float* Wd,
           const float* bq, const float* bk, const float* bv, const float* bd,
           float* Qp, float* Kp, float* Vp)
{
    __shared__ uint32_t As[128][36];
    __shared__ uint32_t Bs[32][72];
    int m0 = blockIdx.y*128, n0 = blockIdx.x*64;
    const float *A1,*B1,*b1,*A2=nullptr,*B2=nullptr,*b2=nullptr; float* C;
    if (blockIdx.z == 0){ A1=q; B1=Wq; b1=bq; C=Qp; }
    else if (blockIdx.z == 1){ A1=k; B1=Wk; b1=bk; A2=pe; B2=Wd; b2=bd; C=Kp; }
    else { A1=v; B1=Wv; b1=bv; C=Vp; }
    gemm_core(A1,B1,b1, A2,B2,b2, C, 1, m0, n0, As, Bs);
}

__global__ __launch_bounds__(256)
void gemm_out(const float* __restrict__ A, const float* __restrict__ Bm,
              const float* __restrict__ bias, float* __restrict__ C)
{
    __shared__ uint32_t As[128][36];
    __shared__ uint32_t Bs[32][72];
    gemm_core(A, Bm, bias, nullptr, nullptr, nullptr, C, 0,
              blockIdx.y*128, blockIdx.x*64, As, Bs);
}

// ---------------- pass 1: rowsum of exp(logits) ----------------
__global__ __launch_bounds__(256)
void attn_rowsum(const float* __restrict__ Q, const float* __restrict__ Kp,
                 float* __restrict__ rsinv)
{
    extern __shared__ uint32_t sm1[];
    uint32_t (*Qs)[68] = (uint32_t(*)[68])sm1;                 // 128x68 tf32
    uint32_t (*Ks)[68] = (uint32_t(*)[68])(sm1 + 128*68);      // 64x68 tf32
    float *rs = (float*)(sm1 + 128*68 + 64*68);                // 128

    int tid = threadIdx.x;
    int lane = tid & 31, wid = tid >> 5;
    int g = lane >> 2, tg = lane & 3;
    int wm = wid & 3, wn = wid >> 2;
    int bh = blockIdx.y;
    int s0 = blockIdx.x * 128;

    const float* Qb = Q  + ((size_t)bh*S_ + s0)*DEPTH;
    const float* Kb = Kp +  (size_t)bh*S_*DEPTH;

    #pragma unroll
    for (int i=0;i<8;i++){
        int e = tid + i*256;
        int r = e>>4, c = (e&15)*4;
        float4 v = *(const float4*)(Qb + (size_t)r*DEPTH + c);
        *(uint4*)&Qs[r][c] = tf4(v);
    }
    if (tid < 128) rs[tid] = 0.f;
    __syncthreads();

    float4 kr[4];
    auto ldgK = [&](int t0){
        #pragma unroll
        for (int i=0;i<4;i++){
            int e = tid + i*256;
            int r = e>>4, c = (e&15)*4;
            kr[i] = *(const float4*)(Kb + (size_t)(t0+r)*DEPTH + c);
        }
    };
    ldgK(0);

    float rowacc[4] = {0.f,0.f,0.f,0.f};

    for (int t0 = 0; t0 < S_; t0 += 64){
        #pragma unroll
        for (int i=0;i<4;i++){
            int e = tid + i*256;
            int r = e>>4, c = (e&15)*4;
            *(uint4*)&Ks[r][c] = tf4(kr[i]);
        }
        __syncthreads();
        if (t0 + 64 < S_) ldgK(t0 + 64);

        float acc[2][4][4];
        #pragma unroll
        for (int i=0;i<2;i++)
            #pragma unroll
            for (int j=0;j<4;j++)
                #pragma unroll
                for (int r=0;r<4;r++) acc[i][j][r]=0.f;

        #pragma unroll
        for (int kk=0; kk<64; kk+=8){
            uint32_t af[2][4];
            #pragma unroll
            for (int mi=0;mi<2;mi++){
                int rb = wm*32 + mi*16;
                af[mi][0]=Qs[rb+g  ][kk+tg  ];
                af[mi][1]=Qs[rb+g+8][kk+tg  ];
                af[mi][2]=Qs[rb+g  ][kk+tg+4];
                af[mi][3]=Qs[rb+g+8][kk+tg+4];
            }
            #pragma unroll
            for (int ni=0;ni<4;ni++){
                int cb = wn*32 + ni*8 + g;        // t index
                uint32_t b0=Ks[cb][kk+tg  ];
                uint32_t b1=Ks[cb][kk+tg+4];
                mma8(acc[0][ni], af[0][0],af[0][1],af[0][2],af[0][3], b0,b1);
                mma8(acc[1][ni], af[1][0],af[1][1],af[1][2],af[1][3], b0,b1);
            }
        }
        #pragma unroll
        for (int mi=0;mi<2;mi++)
            #pragma unroll
            for (int ni=0;ni<4;ni++)
                #pragma unroll
                for (int r2=0;r2<4;r2++){
                    float e_ = __expf(acc[mi][ni][r2]*0.125f);
                    rowacc[mi*2 + (r2>>1)] += e_;
                }
        __syncthreads();   // before Ks is overwritten
    }

    #pragma unroll
    for (int i=0;i<4;i++){
        float v = rowacc[i];
        v += __shfl_xor_sync(0xffffffffu, v, 1);
        v += __shfl_xor_sync(0xffffffffu, v, 2);
        if (tg == 0){
            int row = wm*32 + (i>>1)*16 + g + (i&1)*8;
            atomicAdd(&rs[row], v);
        }
    }
    __syncthreads();
    if (tid < 128) rsinv[(size_t)bh*S_ + s0 + tid] = 1.0f / rs[tid];
}

// ---------------- pass 2: attn write + ctx = attn @ V ----------------
__global__ __launch_bounds__(256)
void attn_pv(const float* __restrict__ Q, const float* __restrict__ Kp,
             const float* __restrict__ V, const float* __restrict__ rsinv,
             float* __restrict__ attn, float* __restrict__ ctx)
{
    extern __shared__ uint32_t sm2[];
    uint32_t (*Qs)[68] = (uint32_t(*)[68])sm2;                          // 128x68
    uint32_t (*Ks)[68] = (uint32_t(*)[68])(sm2 + 128*68);               // 64x68
    uint32_t (*Ps)[68] = (uint32_t(*)[68])(sm2 + 128*68 + 64*68);       // 128x68
    uint32_t (*Vs)[72] = (uint32_t(*)[72])(sm2 + 128*68 + 64*68 + 128*68); // 64x72
    float *rsv = (float*)(sm2 + 128*68 + 64*68 + 128*68 + 64*72);       // 128

    int tid = threadIdx.x;
    int lane = tid & 31, wid = tid >> 5;
    int g = lane >> 2, tg = lane & 3;
    int wm = wid & 3, wn = wid >> 2;
    int bh = blockIdx.y;
    int s0 = blockIdx.x * 128;

    const float* Qb = Q  + ((size_t)bh*S_ + s0)*DEPTH;
    const float* Kb = Kp +  (size_t)bh*S_*DEPTH;
    const float* Vb = V  +  (size_t)bh*S_*DEPTH;

    #pragma unroll
    for (int i=0;i<8;i++){
        int e = tid + i*256;
        int r = e>>4, c = (e&15)*4;
        float4 v = *(const float4*)(Qb + (size_t)r*DEPTH + c);
        *(uint4*)&Qs[r][c] = tf4(v);
    }
    if (tid < 128) rsv[tid] = rsinv[(size_t)bh*S_ + s0 + tid];
    __syncthreads();

    float4 kr[4], vr[4];
    auto ldgKV = [&](int t0){
        #pragma unroll
        for (int i=0;i<4;i++){
            int e = tid + i*256;
            int r = e>>4, c = (e&15)*4;
            kr[i] = *(const float4*)(Kb + (size_t)(t0+r)*DEPTH + c);
            vr[i] = *(const float4*)(Vb + (size_t)(t0+r)*DEPTH + c);
        }
    };
    ldgKV(0);

    float octx[2][4][4];
    #pragma unroll
    for (int i=0;i<2;i++)
        #pragma unroll
        for (int j=0;j<4;j++)
            #pragma unroll
            for (int r=0;r<4;r++) octx[i][j][r]=0.f;

    for (int t0 = 0; t0 < S_; t0 += 64){
        #pragma unroll
        for (int i=0;i<4;i++){
            int e = tid + i*256;
            int r = e>>4, c = (e&15)*4;
            *(uint4*)&Ks[r][c] = tf4(kr[i]);
            *(uint4*)&Vs[r][c] = tf4(vr[i]);
        }
        __syncthreads();
        if (t0 + 64 < S_) ldgKV(t0 + 64);

        float acc[2][4][4];
        #pragma unroll
        for (int i=0;i<2;i++)
            #pragma unroll
            for (int j=0;j<4;j++)
                #pragma unroll
                for (int r=0;r<4;r++) acc[i][j][r]=0.f;

        // logits = Q @ K''^T
        #pragma unroll
        for (int kk=0; kk<64; kk+=8){
            uint32_t af[2][4];
            #pragma unroll
            for (int mi=0;mi<2;mi++){
                int rb = wm*32 + mi*16;
                af[mi][0]=Qs[rb+g  ][kk+tg  ];
                af[mi][1]=Qs[rb+g+8][kk+tg  ];
                af[mi][2]=Qs[rb+g  ][kk+tg+4];
                af[mi][3]=Qs[rb+g+8][kk+tg+4];
            }
            #pragma unroll
            for (int ni=0;ni<4;ni++){
                int cb = wn*32 + ni*8 + g;
                uint32_t b0=Ks[cb][kk+tg  ];
                uint32_t b1=Ks[cb][kk+tg+4];
                mma8(acc[0][ni], af[0][0],af[0][1],af[0][2],af[0][3], b0,b1);
                mma8(acc[1][ni], af[1][0],af[1][1],af[1][2],af[1][3], b0,b1);
            }
        }

        // p = exp(l/8) / rowsum ; write attn (float) + stage P (tf32)
        #pragma unroll
        for (int mi=0;mi<2;mi++){
            int r0 = wm*32 + mi*16 + g;
            float inv0 = rsv[r0], inv1 = rsv[r0+8];
            #pragma unroll
            for (int ni=0;ni<4;ni++){
                acc[mi][ni][0] = __expf(acc[mi][ni][0]*0.125f)*inv0;
                acc[mi][ni][1] = __expf(acc[mi][ni][1]*0.125f)*inv0;
                acc[mi][ni][2] = __expf(acc[mi][ni][2]*0.125f)*inv1;
                acc[mi][ni][3] = __expf(acc[mi][ni][3]*0.125f)*inv1;
            }
        }
        #pragma unroll
        for (int mi=0;mi<2;mi++)
            #pragma unroll
            for (int ni=0;ni<4;ni++)
                #pragma unroll
                for (int half=0; half<2; half++){
                    int rloc = wm*32 + mi*16 + g + half*8;
                    int cloc = wn*32 + ni*8 + tg*2;
                    float2 v2 = make_float2(acc[mi][ni][half*2], acc[mi][ni][half*2+1]);
                    *(uint2*)&Ps[rloc][cloc] = make_uint2(f2tf(v2.x), f2tf(v2.y));
                    size_t aidx = ((size_t)bh*S_ + s0 + rloc)*S_ + t0 + cloc;
                    *(float2*)(attn + aidx) = v2;
                }
        __syncthreads();   // P complete before PV mma

        // ctx += P @ V
        #pragma unroll
        for (int kk=0; kk<64; kk+=8){
            uint32_t af[2][4];
            #pragma unroll
            for (int mi=0;mi<2;mi++){
                int rb = wm*32 + mi*16;
                af[mi][0]=Ps[rb+g  ][kk+tg  ];
                af[mi][1]=Ps[rb+g+8][kk+tg  ];
                af[mi][2]=Ps[rb+g  ][kk+tg+4];
                af[mi][3]=Ps[rb+g+8][kk+tg+4];
            }
            #pragma unroll
            for (int ni=0;ni<4;ni++){
                int cb = wn*32 + ni*8 + g;       // d index
                uint32_t b0=Vs[kk+tg  ][cb];
                uint32_t b1=Vs[kk+tg+4][cb];
                mma8(octx[0][ni], af[0][0],af[0][1],af[0][2],af[0][3], b0,b1);
                mma8(octx[1][ni], af[1][0],af[1][1],af[1][2],af[1][3], b0,b1);
            }
        }
        __syncthreads();   // before Ks/Vs overwritten next iter
    }

    // write ctx in (B,S,D) layout
    int b = bh >> 3, h = bh & 7;
    #pragma unroll
    for (int mi=0;mi<2;mi++)
        #pragma unroll
        for (int ni=0;ni<4;ni++)
            #pragma unroll
            for (int half=0; half<2; half++){
                int row = s0 + wm*32 + mi*16 + g + half*8;
                int col = h*64 + wn*32 + ni*8 + tg*2;
                float2 v2 = make_float2(octx[mi][ni][half*2], octx[mi][ni][half*2+1]);
                *(float2*)(ctx + ((size_t)b*S_ + row)*D_ + col) = v2;
            }
}

// ---------------- launch ----------------
extern "C" void kernel_launch(void* const* d_in, const int* in_sizes, int n_in,
                              void* d_out, int out_size)
{
    const float* q   = (const float*)d_in[0];
    const float* k   = (const float*)d_in[1];
    const float* v   = (const float*)d_in[2];
    const float* pe  = (const float*)d_in[3];
    // d_in[4] = mask (unused by reference)
    const float* Wq  = (const float*)d_in[5];
    const float* bq  = (const float*)d_in[6];
    const float* Wk  = (const float*)d_in[7];
    const float* bk  = (const float*)d_in[8];
    const float* Wv  = (const float*)d_in[9];
    const float* bv  = (const float*)d_in[10];
    const float* Wd  = (const float*)d_in[11];
    const float* bd  = (const float*)d_in[12];

    float* out  = (float*)d_out;                       // (B,S,D)
    float* attn = out + (size_t)B_*S_*D_;              // (B,H,S,S)

    float *Qp, *Kp, *Vp, *Ctx, *Rs;
    cudaGetSymbolAddress((void**)&Qp,  g_Q);
    cudaGetSymbolAddress((void**)&Kp,  g_K);
    cudaGetSymbolAddress((void**)&Vp,  g_V);
    cudaGetSymbolAddress((void**)&Ctx, g_ctx);
    cudaGetSymbolAddress((void**)&Rs,  g_rsinv);

    // Q', K''(=k@Wk+pe@Wd), V' in one launch
    proj3<<<dim3(8, 64, 3), 256>>>(q, k, pe, v, Wq, Wk, Wv, Wd,
                                   bq, bk, bv, bd, Qp, Kp, Vp);

    size_t smA = (size_t)(128*68 + 64*68 + 128) * sizeof(uint32_t);
    cudaFuncSetAttribute(attn_rowsum, cudaFuncAttributeMaxDynamicSharedMemorySize, (int)smA);
    attn_rowsum<<<dim3(16, BH), 256, smA>>>(Qp, Kp, Rs);

    size_t smB = (size_t)(128*68 + 64*68 + 128*68 + 64*72 + 128) * sizeof(uint32_t);
    cudaFuncSetAttribute(attn_pv, cudaFuncAttributeMaxDynamicSharedMemorySize, (int)smB);
    attn_pv<<<dim3(16, BH), 256, smB>>>(Qp, Kp, Vp, Rs, attn, Ctx);

    gemm_out<<<dim3(8, 64), 256>>>(Ctx, Wd, bd, out);
}

// round 3
// speedup vs baseline: 1.2910x; 1.0004x over previous
#include <cuda_runtime.h>
#include <cstdint>
#include <cstddef>

#define B_  4
#define S_  2048
#define D_  512
#define H_  8
#define DEPTH 64
#define BH  (B_*H_)

// ---------------- scratch (no allocations allowed) ----------------
__device__ float g_Q[(size_t)BH*S_*DEPTH];    // Q'  head-split (bh, s, d)
__device__ float g_K[(size_t)BH*S_*DEPTH];    // K'' = k@Wk + pos@Wd (head-split)
__device__ float g_V[(size_t)BH*S_*DEPTH];    // V'  head-split
__device__ float g_ctx[(size_t)B_*S_*D_];     // ctx in (B,S,D) layout
__device__ float g_rsinv[(size_t)BH*S_];      // 1/rowsum

// ---------------- tf32 helpers ----------------
__device__ __forceinline__ uint32_t f2tf(float x){
    uint32_t u; asm("cvt.rna.tf32.f32 %0, %1;" : "=r"(u) : "f"(x)); return u;
}
__device__ __forceinline__ uint4 tf4(float4 v){
    return make_uint4(f2tf(v.x), f2tf(v.y), f2tf(v.z), f2tf(v.w));
}
__device__ __forceinline__ void mma8(float c[4], uint32_t a0,uint32_t a1,uint32_t a2,uint32_t a3,
                                     uint32_t b0,uint32_t b1){
    asm volatile("mma.sync.aligned.m16n8k8.row.col.f32.tf32.tf32.f32 "
        "{%0,%1,%2,%3}, {%4,%5,%6,%7}, {%8,%9}, {%0,%1,%2,%3};"
        : "+f"(c[0]),"+f"(c[1]),"+f"(c[2]),"+f"(c[3])
        : "r"(a0),"r"(a1),"r"(a2),"r"(a3),"r"(b0),"r"(b1));
}

// ---------------- shared GEMM core ----------------
// C[128x64 tile] = A1@B1 (+ A2@B2 if A2) + bias1 (+ bias2)
// A: 8192x512 row-major, B: 512x512 row-major. SMEM tiles hold PRE-CONVERTED tf32.
// split: write head-split (b,h,s,d); else row-major 8192x512.
__device__ __forceinline__ void gemm_core(
    const float* __restrict__ A1, const float* __restrict__ B1, const float* __restrict__ bias1,
    const float* __restrict__ A2, const float* __restrict__ B2, const float* __restrict__ bias2,
    float* __restrict__ C, int split, int m0, int n0,
    uint32_t (*As)[36], uint32_t (*Bs)[72])
{
    int tid = threadIdx.x;
    int lane = tid & 31, wid = tid >> 5;
    int g = lane >> 2, tg = lane & 3;
    int wm = wid & 3, wn = wid >> 2;          // 4x2 warps -> CTA tile 128x64

    float acc[2][4][4];
    #pragma unroll
    for (int i=0;i<2;i++)
        #pragma unroll
        for (int j=0;j<4;j++)
            #pragma unroll
            for (int r=0;r<4;r++) acc[i][j][r]=0.f;

    const int ntile = A2 ? 32 : 16;           // 32-deep k tiles

    float4 ra[4]; float4 rb[2];
    auto ldg_tile = [&](int t){
        const float* A  = (t >= 16) ? A2 : A1;
        const float* Bm = (t >= 16) ? B2 : B1;
        int k0 = (t & 15) * 32;
        #pragma unroll
        for (int i=0;i<4;i++){                 // A: 128x32
            int e = tid + i*256;
            int r = e>>3, c = (e&7)*4;
            ra[i] = *(const float4*)(A + (size_t)(m0+r)*512 + k0 + c);
        }
        #pragma unroll
        for (int i=0;i<2;i++){                 // B: 32x64
            int e = tid + i*256;
            int r = e>>4, c = (e&15)*4;
            rb[i] = *(const float4*)(Bm + (size_t)(k0+r)*512 + n0 + c);
        }
    };

    ldg_tile(0);
    for (int t = 0; t < ntile; t++){
        #pragma unroll
        for (int i=0;i<4;i++){
            int e = tid + i*256;
            int r = e>>3, c = (e&7)*4;
            *(uint4*)&As[r][c] = tf4(ra[i]);
        }
        #pragma unroll
        for (int i=0;i<2;i++){
            int e = tid + i*256;
            int r = e>>4, c = (e&15)*4;
            *(uint4*)&Bs[r][c] = tf4(rb[i]);
        }
        __syncthreads();
        if (t+1 < ntile) ldg_tile(t+1);        // overlap LDG with mma
        #pragma unroll
        for (int kk=0; kk<32; kk+=8){
            uint32_t af[2][4];
            #pragma unroll
            for (int mi=0;mi<2;mi++){
                int rb_ = wm*32 + mi*16;
                af[mi][0]=As[rb_+g  ][kk+tg  ];
                af[mi][1]=As[rb_+g+8][kk+tg  ];
                af[mi][2]=As[rb_+g  ][kk+tg+4];
                af[mi][3]=As[rb_+g+8][kk+tg+4];
            }
            #pragma unroll
            for (int ni=0;ni<4;ni++){
                int cb = wn*32 + ni*8 + g;
                uint32_t b0=Bs[kk+tg  ][cb];
                uint32_t b1=Bs[kk+tg+4][cb];
                mma8(acc[0][ni], af[0][0],af[0][1],af[0][2],af[0][3], b0,b1);
                mma8(acc[1][ni], af[1][0],af[1][1],af[1][2],af[1][3], b0,b1);
            }
        }
        __syncthreads();
    }

    #pragma unroll
    for (int mi=0;mi<2;mi++)
        #pragma unroll
        for (int ni=0;ni<4;ni++)
            #pragma unroll
            for (int half=0; half<2; half++){
                int row = m0 + wm*32 + mi*16 + g + half*8;
                int col = n0 + wn*32 + ni*8 + tg*2;
                float b0v = bias1[col]   + (bias2 ? bias2[col]   : 0.f);
                float b1v = bias1[col+1] + (bias2 ? bias2[col+1] : 0.f);
                float v0 = acc[mi][ni][half*2+0] + b0v;
                float v1 = acc[mi][ni][half*2+1] + b1v;
                size_t idx;
                if (split){
                    int b = row >> 11, s = row & 2047;
                    int h = col >> 6,  d = col & 63;
                    idx = (((size_t)(b*H_ + h))*S_ + s)*DEPTH + d;
                } else {
                    idx = (size_t)row*512 + col;
                }
                *(float2*)(C + idx) = make_float2(v0, v1);
            }
}

// z=0: Q'=q@Wq+bq   z=1: K''=k@Wk+pe@Wd+bk+bd   z=2: V'=v@Wv+bv
__global__ __launch_bounds__(256)
void proj3(const float* q, const float* k, const float* pe, const float* v,
           const float* Wq, const float* Wk, const float* Wv, const float* Wd,
           const float* bq, const float* bk, const float* bv, const float* bd,
           float* Qp, float* Kp, float* Vp)
{
    __shared__ uint32_t As[128][36];
    __shared__ uint32_t Bs[32][72];
    int m0 = blockIdx.y*128, n0 = blockIdx.x*64;
    const float *A1,*B1,*b1,*A2=nullptr,*B2=nullptr,*b2=nullptr; float* C;
    if (blockIdx.z == 0){ A1=q; B1=Wq; b1=bq; C=Qp; }
    else if (blockIdx.z == 1){ A1=k; B1=Wk; b1=bk; A2=pe; B2=Wd; b2=bd; C=Kp; }
    else { A1=v; B1=Wv; b1=bv; C=Vp; }
    gemm_core(A1,B1,b1, A2,B2,b2, C, 1, m0, n0, As, Bs);
}

__global__ __launch_bounds__(256)
void gemm_out(const float* __restrict__ A, const float* __restrict__ Bm,
              const float* __restrict__ bias, float* __restrict__ C)
{
    __shared__ uint32_t As[128][36];
    __shared__ uint32_t Bs[32][72];
    gemm_core(A, Bm, bias, nullptr, nullptr, nullptr, C, 0,
              blockIdx.y*128, blockIdx.x*64, As, Bs);
}

// ---------------- pass 1: rowsum of exp(logits) ----------------
__global__ __launch_bounds__(256)
void attn_rowsum(const float* __restrict__ Q, const float* __restrict__ Kp,
                 float* __restrict__ rsinv)
{
    extern __shared__ uint32_t sm1[];
    uint32_t (*Qs)[68] = (uint32_t(*)[68])sm1;                 // 128x68 tf32
    uint32_t (*Ks)[68] = (uint32_t(*)[68])(sm1 + 128*68);      // 64x68 tf32
    float *rs = (float*)(sm1 + 128*68 + 64*68);                // 128

    int tid = threadIdx.x;
    int lane = tid & 31, wid = tid >> 5;
    int g = lane >> 2, tg = lane & 3;
    int wm = wid & 3, wn = wid >> 2;
    int bh = blockIdx.y;
    int s0 = blockIdx.x * 128;

    const float* Qb = Q  + ((size_t)bh*S_ + s0)*DEPTH;
    const float* Kb = Kp +  (size_t)bh*S_*DEPTH;

    #pragma unroll
    for (int i=0;i<8;i++){
        int e = tid + i*256;
        int r = e>>4, c = (e&15)*4;
        float4 v = *(const float4*)(Qb + (size_t)r*DEPTH + c);
        *(uint4*)&Qs[r][c] = tf4(v);
    }
    if (tid < 128) rs[tid] = 0.f;
    __syncthreads();

    float4 kr[4];
    auto ldgK = [&](int t0){
        #pragma unroll
        for (int i=0;i<4;i++){
            int e = tid + i*256;
            int r = e>>4, c = (e&15)*4;
            kr[i] = *(const float4*)(Kb + (size_t)(t0+r)*DEPTH + c);
        }
    };
    ldgK(0);

    float rowacc[4] = {0.f,0.f,0.f,0.f};

    for (int t0 = 0; t0 < S_; t0 += 64){
        #pragma unroll
        for (int i=0;i<4;i++){
            int e = tid + i*256;
            int r = e>>4, c = (e&15)*4;
            *(uint4*)&Ks[r][c] = tf4(kr[i]);
        }
        __syncthreads();
        if (t0 + 64 < S_) ldgK(t0 + 64);

        float acc[2][4][4];
        #pragma unroll
        for (int i=0;i<2;i++)
            #pragma unroll
            for (int j=0;j<4;j++)
                #pragma unroll
                for (int r=0;r<4;r++) acc[i][j][r]=0.f;

        #pragma unroll
        for (int kk=0; kk<64; kk+=8){
            uint32_t af[2][4];
            #pragma unroll
            for (int mi=0;mi<2;mi++){
                int rb = wm*32 + mi*16;
                af[mi][0]=Qs[rb+g  ][kk+tg  ];
                af[mi][1]=Qs[rb+g+8][kk+tg  ];
                af[mi][2]=Qs[rb+g  ][kk+tg+4];
                af[mi][3]=Qs[rb+g+8][kk+tg+4];
            }
            #pragma unroll
            for (int ni=0;ni<4;ni++){
                int cb = wn*32 + ni*8 + g;        // t index
                uint32_t b0=Ks[cb][kk+tg  ];
                uint32_t b1=Ks[cb][kk+tg+4];
                mma8(acc[0][ni], af[0][0],af[0][1],af[0][2],af[0][3], b0,b1);
                mma8(acc[1][ni], af[1][0],af[1][1],af[1][2],af[1][3], b0,b1);
            }
        }
        #pragma unroll
        for (int mi=0;mi<2;mi++)
            #pragma unroll
            for (int ni=0;ni<4;ni++)
                #pragma unroll
                for (int r2=0;r2<4;r2++){
                    float e_ = __expf(acc[mi][ni][r2]*0.125f);
                    rowacc[mi*2 + (r2>>1)] += e_;
                }
        __syncthreads();   // before Ks is overwritten
    }

    #pragma unroll
    for (int i=0;i<4;i++){
        float v = rowacc[i];
        v += __shfl_xor_sync(0xffffffffu, v, 1);
        v += __shfl_xor_sync(0xffffffffu, v, 2);
        if (tg == 0){
            int row = wm*32 + (i>>1)*16 + g + (i&1)*8;
            atomicAdd(&rs[row], v);
        }
    }
    __syncthreads();
    if (tid < 128) rsinv[(size_t)bh*S_ + s0 + tid] = 1.0f / rs[tid];
}

// ---------------- pass 2: attn write + ctx = attn @ V ----------------
__global__ __launch_bounds__(256)
void attn_pv(const float* __restrict__ Q, const float* __restrict__ Kp,
             const float* __restrict__ V, const float* __restrict__ rsinv,
             float* __restrict__ attn, float* __restrict__ ctx)
{
    extern __shared__ uint32_t sm2[];
    uint32_t (*Qs)[68] = (uint32_t(*)[68])sm2;                          // 128x68
    uint32_t (*Ks)[68] = (uint32_t(*)[68])(sm2 + 128*68);               // 64x68
    uint32_t (*Ps)[68] = (uint32_t(*)[68])(sm2 + 128*68 + 64*68);       // 128x68
    uint32_t (*Vs)[72] = (uint32_t(*)[72])(sm2 + 128*68 + 64*68 + 128*68); // 64x72
    float *rsv = (float*)(sm2 + 128*68 + 64*68 + 128*68 + 64*72);       // 128

    int tid = threadIdx.x;
    int lane = tid & 31, wid = tid >> 5;
    int g = lane >> 2, tg = lane & 3;
    int wm = wid & 3, wn = wid >> 2;
    int bh = blockIdx.y;
    int s0 = blockIdx.x * 128;

    const float* Qb = Q  + ((size_t)bh*S_ + s0)*DEPTH;
    const float* Kb = Kp +  (size_t)bh*S_*DEPTH;
    const float* Vb = V  +  (size_t)bh*S_*DEPTH;

    #pragma unroll
    for (int i=0;i<8;i++){
        int e = tid + i*256;
        int r = e>>4, c = (e&15)*4;
        float4 v = *(const float4*)(Qb + (size_t)r*DEPTH + c);
        *(uint4*)&Qs[r][c] = tf4(v);
    }
    if (tid < 128) rsv[tid] = rsinv[(size_t)bh*S_ + s0 + tid];
    __syncthreads();

    float4 kr[4], vr[4];
    auto ldgKV = [&](int t0){
        #pragma unroll
        for (int i=0;i<4;i++){
            int e = tid + i*256;
            int r = e>>4, c = (e&15)*4;
            kr[i] = *(const float4*)(Kb + (size_t)(t0+r)*DEPTH + c);
            vr[i] = *(const float4*)(Vb + (size_t)(t0+r)*DEPTH + c);
        }
    };
    ldgKV(0);

    float octx[2][4][4];
    #pragma unroll
    for (int i=0;i<2;i++)
        #pragma unroll
        for (int j=0;j<4;j++)
            #pragma unroll
            for (int r=0;r<4;r++) octx[i][j][r]=0.f;

    for (int t0 = 0; t0 < S_; t0 += 64){
        #pragma unroll
        for (int i=0;i<4;i++){
            int e = tid + i*256;
            int r = e>>4, c = (e&15)*4;
            *(uint4*)&Ks[r][c] = tf4(kr[i]);
            *(uint4*)&Vs[r][c] = tf4(vr[i]);
        }
        __syncthreads();
        if (t0 + 64 < S_) ldgKV(t0 + 64);

        float acc[2][4][4];
        #pragma unroll
        for (int i=0;i<2;i++)
            #pragma unroll
            for (int j=0;j<4;j++)
                #pragma unroll
                for (int r=0;r<4;r++) acc[i][j][r]=0.f;

        // logits = Q @ K''^T
        #pragma unroll
        for (int kk=0; kk<64; kk+=8){
            uint32_t af[2][4];
            #pragma unroll
            for (int mi=0;mi<2;mi++){
                int rb = wm*32 + mi*16;
                af[mi][0]=Qs[rb+g  ][kk+tg  ];
                af[mi][1]=Qs[rb+g+8][kk+tg  ];
                af[mi][2]=Qs[rb+g  ][kk+tg+4];
                af[mi][3]=Qs[rb+g+8][kk+tg+4];
            }
            #pragma unroll
            for (int ni=0;ni<4;ni++){
                int cb = wn*32 + ni*8 + g;
                uint32_t b0=Ks[cb][kk+tg  ];
                uint32_t b1=Ks[cb][kk+tg+4];
                mma8(acc[0][ni], af[0][0],af[0][1],af[0][2],af[0][3], b0,b1);
                mma8(acc[1][ni], af[1][0],af[1][1],af[1][2],af[1][3], b0,b1);
            }
        }

        // p = exp(l/8) / rowsum ; write attn (float) + stage P (tf32)
        #pragma unroll
        for (int mi=0;mi<2;mi++){
            int r0 = wm*32 + mi*16 + g;
            float inv0 = rsv[r0], inv1 = rsv[r0+8];
            #pragma unroll
            for (int ni=0;ni<4;ni++){
                acc[mi][ni][0] = __expf(acc[mi][ni][0]*0.125f)*inv0;
                acc[mi][ni][1] = __expf(acc[mi][ni][1]*0.125f)*inv0;
                acc[mi][ni][2] = __expf(acc[mi][ni][2]*0.125f)*inv1;
                acc[mi][ni][3] = __expf(acc[mi][ni][3]*0.125f)*inv1;
            }
        }
        #pragma unroll
        for (int mi=0;mi<2;mi++)
            #pragma unroll
            for (int ni=0;ni<4;ni++)
                #pragma unroll
                for (int half=0; half<2; half++){
                    int rloc = wm*32 + mi*16 + g + half*8;
                    int cloc = wn*32 + ni*8 + tg*2;
                    float2 v2 = make_float2(acc[mi][ni][half*2], acc[mi][ni][half*2+1]);
                    *(uint2*)&Ps[rloc][cloc] = make_uint2(f2tf(v2.x), f2tf(v2.y));
                    size_t aidx = ((size_t)bh*S_ + s0 + rloc)*S_ + t0 + cloc;
                    *(float2*)(attn + aidx) = v2;
                }
        __syncthreads();   // P complete before PV mma

        // ctx += P @ V
        #pragma unroll
        for (int kk=0; kk<64; kk+=8){
            uint32_t af[2][4];
            #pragma unroll
            for (int mi=0;mi<2;mi++){
                int rb = wm*32 + mi*16;
                af[mi][0]=Ps[rb+g  ][kk+tg  ];
                af[mi][1]=Ps[rb+g+8][kk+tg  ];
                af[mi][2]=Ps[rb+g  ][kk+tg+4];
                af[mi][3]=Ps[rb+g+8][kk+tg+4];
            }
            #pragma unroll
            for (int ni=0;ni<4;ni++){
                int cb = wn*32 + ni*8 + g;       // d index
                uint32_t b0=Vs[kk+tg  ][cb];
                uint32_t b1=Vs[kk+tg+4][cb];
                mma8(octx[0][ni], af[0][0],af[0][1],af[0][2],af[0][3], b0,b1);
                mma8(octx[1][ni], af[1][0],af[1][1],af[1][2],af[1][3], b0,b1);
            }
        }
        __syncthreads();   // before Ks/Vs overwritten next iter
    }

    // write ctx in (B,S,D) layout
    int b = bh >> 3, h = bh & 7;
    #pragma unroll
    for (int mi=0;mi<2;mi++)
        #pragma unroll
        for (int ni=0;ni<4;ni++)
            #pragma unroll
            for (int half=0; half<2; half++){
                int row = s0 + wm*32 + mi*16 + g + half*8;
                int col = h*64 + wn*32 + ni*8 + tg*2;
                float2 v2 = make_float2(octx[mi][ni][half*2], octx[mi][ni][half*2+1]);
                *(float2*)(ctx + ((size_t)b*S_ + row)*D_ + col) = v2;
            }
}

// ---------------- launch ----------------
extern "C" void kernel_launch(void* const* d_in, const int* in_sizes, int n_in,
                              void* d_out, int out_size)
{
    const float* q   = (const float*)d_in[0];
    const float* k   = (const float*)d_in[1];
    const float* v   = (const float*)d_in[2];
    const float* pe  = (const float*)d_in[3];
    // d_in[4] = mask (unused by reference)
    const float* Wq  = (const float*)d_in[5];
    const float* bq  = (const float*)d_in[6];
    const float* Wk  = (const float*)d_in[7];
    const float* bk  = (const float*)d_in[8];
    const float* Wv  = (const float*)d_in[9];
    const float* bv  = (const float*)d_in[10];
    const float* Wd  = (const float*)d_in[11];
    const float* bd  = (const float*)d_in[12];

    float* out  = (float*)d_out;                       // (B,S,D)
    float* attn = out + (size_t)B_*S_*D_;              // (B,H,S,S)

    float *Qp, *Kp, *Vp, *Ctx, *Rs;
    cudaGetSymbolAddress((void**)&Qp,  g_Q);
    cudaGetSymbolAddress((void**)&Kp,  g_K);
    cudaGetSymbolAddress((void**)&Vp,  g_V);
    cudaGetSymbolAddress((void**)&Ctx, g_ctx);
    cudaGetSymbolAddress((void**)&Rs,  g_rsinv);

    // Q', K''(=k@Wk+pe@Wd), V' in one launch
    proj3<<<dim3(8, 64, 3), 256>>>(q, k, pe, v, Wq, Wk, Wv, Wd,
                                   bq, bk, bv, bd, Qp, Kp, Vp);

    size_t smA = (size_t)(128*68 + 64*68 + 128) * sizeof(uint32_t);
    cudaFuncSetAttribute(attn_rowsum, cudaFuncAttributeMaxDynamicSharedMemorySize, (int)smA);
    attn_rowsum<<<dim3(16, BH), 256, smA>>>(Qp, Kp, Rs);

    size_t smB = (size_t)(128*68 + 64*68 + 128*68 + 64*72 + 128) * sizeof(uint32_t);
    cudaFuncSetAttribute(attn_pv, cudaFuncAttributeMaxDynamicSharedMemorySize, (int)smB);
    attn_pv<<<dim3(16, BH), 256, smB>>>(Qp, Kp, Vp, Rs, attn, Ctx);

    gemm_out<<<dim3(8, 64), 256>>>(Ctx, Wd, bd, out);
}